// round 2
// baseline (speedup 1.0000x reference)
#include <cuda_runtime.h>
#include <math.h>

#define BB   8192
#define SS   512
#define KK   8
#define HH   512
#define NC   8704          // S*(2K+1)
#define EPSK 1e-6f

// scratch (static device globals — no allocations)
__device__ float g_hid[(size_t)BB * HH];   // 16 MB
__device__ float g_net[(size_t)BB * NC];   // 285 MB

// ---------------------------------------------------------------------------
// C = tanh(A @ B + bias)   A: MxK row-major (lda), B: KxN row-major, C: MxN
// 128x128 tile, Kt=8, 256 threads, 8x8 per-thread micro-tile, double-buffered.
// All dims are multiples of tile sizes — no guards.
// ---------------------------------------------------------------------------
template <bool SUB_HALF>
__global__ __launch_bounds__(256, 2)
void sgemm_tanh_kernel(const float* __restrict__ A, const float* __restrict__ Bm,
                       const float* __restrict__ bias, float* __restrict__ C,
                       int M, int N, int K, int lda)
{
    __shared__ float As[2][8][128];   // [k][m]
    __shared__ float Bs[2][8][128];   // [k][n]

    const int tid = threadIdx.x;
    const int tx  = tid & 15;         // 16 col-groups
    const int ty  = tid >> 4;         // 16 row-groups
    const int mBase = blockIdx.y * 128;
    const int nBase = blockIdx.x * 128;

    // A tile loader: 128 rows x 8 k, one float4 per thread
    const int arow = tid >> 1;
    const int acol = (tid & 1) << 2;
    // B tile loader: 8 rows x 128 cols, one float4 per thread
    const int brow = tid >> 5;
    const int bcol = (tid & 31) << 2;

    const float* Aptr = A  + (size_t)(mBase + arow) * lda + acol;
    const float* Bptr = Bm + (size_t)brow * N + nBase + bcol;

    float acc[8][8];
    #pragma unroll
    for (int i = 0; i < 8; i++)
        #pragma unroll
        for (int j = 0; j < 8; j++) acc[i][j] = 0.f;

    float4 pA = *(const float4*)Aptr;
    if (SUB_HALF) { pA.x -= 0.5f; pA.y -= 0.5f; pA.z -= 0.5f; pA.w -= 0.5f; }
    float4 pB = *(const float4*)Bptr;

    As[0][acol + 0][arow] = pA.x;
    As[0][acol + 1][arow] = pA.y;
    As[0][acol + 2][arow] = pA.z;
    As[0][acol + 3][arow] = pA.w;
    *(float4*)&Bs[0][brow][bcol] = pB;
    __syncthreads();

    int buf = 0;
    const int nT = K >> 3;
    for (int t = 0; t < nT; t++) {
        if (t + 1 < nT) {
            pA = *(const float4*)(Aptr + (t + 1) * 8);
            if (SUB_HALF) { pA.x -= 0.5f; pA.y -= 0.5f; pA.z -= 0.5f; pA.w -= 0.5f; }
            pB = *(const float4*)(Bptr + (size_t)(t + 1) * 8 * N);
        }
        #pragma unroll
        for (int kt = 0; kt < 8; kt++) {
            float4 a0 = *(const float4*)&As[buf][kt][ty * 4];
            float4 a1 = *(const float4*)&As[buf][kt][ty * 4 + 64];
            float4 b0 = *(const float4*)&Bs[buf][kt][tx * 4];
            float4 b1 = *(const float4*)&Bs[buf][kt][tx * 4 + 64];
            float a[8] = {a0.x, a0.y, a0.z, a0.w, a1.x, a1.y, a1.z, a1.w};
            float b[8] = {b0.x, b0.y, b0.z, b0.w, b1.x, b1.y, b1.z, b1.w};
            #pragma unroll
            for (int i = 0; i < 8; i++)
                #pragma unroll
                for (int j = 0; j < 8; j++)
                    acc[i][j] = fmaf(a[i], b[j], acc[i][j]);
        }
        if (t + 1 < nT) {
            const int nb = buf ^ 1;
            As[nb][acol + 0][arow] = pA.x;
            As[nb][acol + 1][arow] = pA.y;
            As[nb][acol + 2][arow] = pA.z;
            As[nb][acol + 3][arow] = pA.w;
            *(float4*)&Bs[nb][brow][bcol] = pB;
            __syncthreads();
            buf = nb;
        }
    }

    float bb[8];
    *(float4*)&bb[0] = *(const float4*)&bias[nBase + tx * 4];
    *(float4*)&bb[4] = *(const float4*)&bias[nBase + 64 + tx * 4];

    #pragma unroll
    for (int i = 0; i < 8; i++) {
        const int row = mBase + ((i < 4) ? (ty * 4 + i) : (64 + ty * 4 + i - 4));
        float4 o0, o1;
        o0.x = tanhf(acc[i][0] + bb[0]);
        o0.y = tanhf(acc[i][1] + bb[1]);
        o0.z = tanhf(acc[i][2] + bb[2]);
        o0.w = tanhf(acc[i][3] + bb[3]);
        o1.x = tanhf(acc[i][4] + bb[4]);
        o1.y = tanhf(acc[i][5] + bb[5]);
        o1.z = tanhf(acc[i][6] + bb[6]);
        o1.w = tanhf(acc[i][7] + bb[7]);
        float* Crow = C + (size_t)row * N + nBase;
        *(float4*)&Crow[tx * 4]      = o0;
        *(float4*)&Crow[64 + tx * 4] = o1;
    }
}

// ---------------------------------------------------------------------------
// Spline epilogue: one block per batch row b (512 threads, one per s).
// Reads net[b, s, 0:17], computes phi_b and the per-(b,s) log term;
// block-reduces the log sum; copies x_a into the output.
// ---------------------------------------------------------------------------
__global__ __launch_bounds__(512)
void spline_epilogue_kernel(const float* __restrict__ x_input,
                            const float* __restrict__ log_density,
                            const float* __restrict__ net,
                            float* __restrict__ out)
{
    const int b = blockIdx.x;
    const int s = threadIdx.x;

    const float* np = net + (size_t)b * NC + s * 17;
    float v[17];
    #pragma unroll
    for (int j = 0; j < 17; j++) v[j] = np[j];

    // softmax over w_raw = v[9..16]
    float m = v[9];
    #pragma unroll
    for (int j = 10; j < 17; j++) m = fmaxf(m, v[j]);
    float w[8];
    float wsum = 0.f;
    #pragma unroll
    for (int j = 0; j < 8; j++) { w[j] = __expf(v[9 + j] - m); wsum += w[j]; }
    const float winv = 1.f / wsum;
    #pragma unroll
    for (int j = 0; j < 8; j++) w[j] *= winv;

    // h_norm
    float eh[9];
    #pragma unroll
    for (int j = 0; j < 9; j++) eh[j] = __expf(v[j]);
    float denom = 0.f;
    #pragma unroll
    for (int i = 0; i < 8; i++) denom += 0.5f * w[i] * (eh[i] + eh[i + 1]);
    const float dinv = 1.f / denom;
    float h[9];
    #pragma unroll
    for (int i = 0; i < 9; i++) h[i] = eh[i] * dinv;

    const float xa = x_input[(size_t)b * (2 * SS) + s];
    const float xb = x_input[(size_t)b * (2 * SS) + SS + s];

    // bin index: count knots < xb, knots = [-eps, cumsum(w)]
    int cnt = (-EPSK < xb) ? 1 : 0;
    float cs = 0.f;
    #pragma unroll
    for (int i = 0; i < 8; i++) { cs += w[i]; cnt += (cs < xb) ? 1 : 0; }
    int k = cnt - 1;
    k = k < 0 ? 0 : (k > 7 ? 7 : k);

    // gather bin parameters (unrolled predicated selection; no local-mem arrays)
    float xk = 0.f, pk = 0.f, wk = 0.f, hk = 0.f, hk1 = 0.f;
    #pragma unroll
    for (int i = 0; i < 8; i++) {
        const float area = 0.5f * w[i] * (h[i] + h[i + 1]);
        if (i < k)  { xk += w[i]; pk += area; }
        if (i == k) { wk = w[i]; hk = h[i]; hk1 = h[i + 1]; }
    }
    if (k == 0) xk = -EPSK;

    const float alpha = (xb - xk) / wk;
    const float phib  = pk + alpha * hk * wk + 0.5f * alpha * alpha * (hk1 - hk) * wk;
    const float lt    = __logf(fmaf(alpha, (hk1 - hk), hk));

    out[(size_t)b * (2 * SS) + s]      = xa;
    out[(size_t)b * (2 * SS) + SS + s] = phib;

    // block-reduce the log terms
    __shared__ float red[16];
    float sum = lt;
    #pragma unroll
    for (int o = 16; o > 0; o >>= 1) sum += __shfl_xor_sync(0xffffffffu, sum, o);
    const int lane = s & 31, wid = s >> 5;
    if (lane == 0) red[wid] = sum;
    __syncthreads();
    if (s < 16) {
        float t = red[s];
        #pragma unroll
        for (int o = 8; o > 0; o >>= 1) t += __shfl_xor_sync(0xffffu, t, o);
        if (s == 0) out[(size_t)BB * (2 * SS) + b] = log_density[b] - t;
    }
}

// ---------------------------------------------------------------------------
extern "C" void kernel_launch(void* const* d_in, const int* in_sizes, int n_in,
                              void* d_out, int out_size)
{
    const float* x   = (const float*)d_in[0];  // (B, 2S)
    const float* ld  = (const float*)d_in[1];  // (B, 1)
    const float* W1  = (const float*)d_in[2];  // (S, H)
    const float* b1  = (const float*)d_in[3];  // (H,)
    const float* W2  = (const float*)d_in[4];  // (H, S*(2K+1))
    const float* b2  = (const float*)d_in[5];  // (S*(2K+1),)
    float* out = (float*)d_out;

    float *hid, *net;
    cudaGetSymbolAddress((void**)&hid, g_hid);
    cudaGetSymbolAddress((void**)&net, g_net);

    // hid = tanh((x_a - 0.5) @ W1 + b1):  M=8192, N=512, K=512, lda=1024
    sgemm_tanh_kernel<true><<<dim3(HH / 128, BB / 128), 256>>>(
        x, W1, b1, hid, BB, HH, SS, 2 * SS);

    // net = tanh(hid @ W2 + b2):  M=8192, N=8704, K=512
    sgemm_tanh_kernel<false><<<dim3(NC / 128, BB / 128), 256>>>(
        hid, W2, b2, net, BB, NC, HH, HH);

    // spline evaluation + log-det reduction + x_a passthrough
    spline_epilogue_kernel<<<BB, 512>>>(x, ld, net, out);
}

// round 4
// speedup vs baseline: 1.7535x; 1.7535x over previous
#include <cuda_runtime.h>
#include <cuda_bf16.h>
#include <stdint.h>
#include <math.h>

#define BB   8192
#define HH   512
#define NCC  8704          // S*(2K+1)
#define KP   1536          // 3x bf16-split K
#define EPSK 1e-6f

// stage: A 128 rows * 80B + B 128 rows * 80B
#define ROWB   80
#define ASTG   (128 * ROWB)        // 10240
#define STGB   (2 * ASTG)          // 20480
#define NSTG   4
#define DSMEM  (NSTG * STGB)       // 81920

__device__ __align__(128) float         g_hid[(size_t)BB * HH];
__device__ __align__(128) float         g_net[(size_t)BB * NCC];
__device__ __align__(128) __nv_bfloat16 g_A1[(size_t)BB * KP];
__device__ __align__(128) __nv_bfloat16 g_A2[(size_t)BB * KP];
__device__ __align__(128) __nv_bfloat16 g_B1[(size_t)HH * KP];
__device__ __align__(128) __nv_bfloat16 g_B2[(size_t)NCC * KP];

// ------------------------------ helpers ------------------------------------
__device__ __forceinline__ uint32_t smem_u32(const void* p) {
    uint32_t a;
    asm("{ .reg .u64 t; cvta.to.shared.u64 t, %1; cvt.u32.u64 %0, t; }" : "=r"(a) : "l"(p));
    return a;
}
#define CP16(dst, src) \
    asm volatile("cp.async.cg.shared.global [%0], [%1], 16;" :: "r"(dst), "l"(src))
#define CP_COMMIT() asm volatile("cp.async.commit_group;" ::: "memory")
#define CP_WAIT2()  asm volatile("cp.async.wait_group 2;" ::: "memory")

__device__ __forceinline__ void ldm_x4(uint32_t* r, uint32_t addr) {
    asm volatile("ldmatrix.sync.aligned.m8n8.x4.shared.b16 {%0,%1,%2,%3}, [%4];"
                 : "=r"(r[0]), "=r"(r[1]), "=r"(r[2]), "=r"(r[3]) : "r"(addr));
}
__device__ __forceinline__ void mma16816(float* c, const uint32_t* a, const uint32_t* b) {
    asm volatile(
        "mma.sync.aligned.m16n8k16.row.col.f32.bf16.bf16.f32 "
        "{%0,%1,%2,%3}, {%4,%5,%6,%7}, {%8,%9}, {%0,%1,%2,%3};"
        : "+f"(c[0]), "+f"(c[1]), "+f"(c[2]), "+f"(c[3])
        : "r"(a[0]), "r"(a[1]), "r"(a[2]), "r"(a[3]), "r"(b[0]), "r"(b[1]));
}

// accurate fast tanh: (e^{2x}-1)/(e^{2x}+1)
__device__ __forceinline__ float tanh_acc(float x) {
    float y = fminf(fmaxf(2.0f * x, -60.0f), 60.0f);
    float t = __expf(y);
    return __fdividef(t - 1.0f, t + 1.0f);
}

// ---------------------------------------------------------------------------
// C[m][n] = tanh(sum_k A'[m][k] * B'[n][k] + bias[n])
// A' [M,KP] bf16 row-major, B' [N,KP] bf16 row-major (K-major both).
// CTA tile 128x128, 8 warps (2 m-groups x 4 n-groups), warp tile 64x32,
// BK=32, 4-stage cp.async pipeline, mma.sync m16n8k16 bf16.
// ---------------------------------------------------------------------------
__global__ __launch_bounds__(256, 2)
void gemm_tc(const __nv_bfloat16* __restrict__ A, const __nv_bfloat16* __restrict__ Bm,
             const float* __restrict__ bias, float* __restrict__ C, int Ng)
{
    extern __shared__ char dyn[];
    const uint32_t dynB = smem_u32(dyn);
    const int tid  = threadIdx.x;
    const int lane = tid & 31, w = tid >> 5;
    const int warp_m = w & 1, warp_n = w >> 1;         // 2 x 4
    const int mBase = blockIdx.y * 128, nBase = blockIdx.x * 128;

    const char* Ag = (const char*)(A  + (size_t)mBase * KP);
    const char* Bg = (const char*)(Bm + (size_t)nBase * KP);

    // loader mapping: thread -> (row, 16B chunk), 2 row-passes
    const int lrow = tid >> 2;          // 0..63
    const int lch  = (tid & 3) * 16;    // byte offset in 64B k-slab

#define LOAD_STAGE(c) do {                                                       \
    const int _s = (c) & 3;                                                      \
    const uint32_t _as = dynB + _s * STGB;                                       \
    const uint32_t _bs = _as + ASTG;                                             \
    const size_t _kb = (size_t)(c) * 64;                                         \
    _Pragma("unroll")                                                            \
    for (int _h = 0; _h < 2; _h++) {                                             \
        const int _r = lrow + _h * 64;                                           \
        CP16(_as + _r * ROWB + lch, Ag + (size_t)_r * (KP * 2) + _kb + lch);     \
        CP16(_bs + _r * ROWB + lch, Bg + (size_t)_r * (KP * 2) + _kb + lch);     \
    }                                                                            \
    CP_COMMIT();                                                                 \
} while (0)

    LOAD_STAGE(0); LOAD_STAGE(1); LOAD_STAGE(2);

    float acc[4][4][4];
    #pragma unroll
    for (int i = 0; i < 4; i++)
        #pragma unroll
        for (int j = 0; j < 4; j++)
            #pragma unroll
            for (int e = 0; e < 4; e++) acc[i][j][e] = 0.f;

    // ldmatrix address components (per lane)
    const int grp = lane >> 3, lr = lane & 7;
    // A: g0=(m0-7,k0) g1=(m8-15,k0) g2=(m0-7,k8) g3=(m8-15,k8)
    const int a_row = warp_m * 64 + (grp & 1) * 8 + lr;
    const int a_kb  = (grp >> 1) * 16;
    // B: g0=(n0-7,k0) g1=(n0-7,k8) g2=(n8-15,k0) g3=(n8-15,k8)
    const int b_row = warp_n * 32 + (grp >> 1) * 8 + lr;
    const int b_kb  = (grp & 1) * 16;

    const int NIT = KP / 32;   // 48
    for (int c = 0; c < NIT; c++) {
        CP_WAIT2();
        __syncthreads();
        if (c + 3 < NIT) LOAD_STAGE(c + 3);

        const uint32_t as = dynB + (c & 3) * STGB;
        const uint32_t bs = as + ASTG;

        #pragma unroll
        for (int kk = 0; kk < 2; kk++) {
            uint32_t a[4][4], b[4][2];
            #pragma unroll
            for (int i = 0; i < 4; i++)
                ldm_x4(a[i], as + (uint32_t)(a_row + i * 16) * ROWB + kk * 32 + a_kb);
            #pragma unroll
            for (int p = 0; p < 2; p++) {
                uint32_t r[4];
                ldm_x4(r, bs + (uint32_t)(b_row + p * 16) * ROWB + kk * 32 + b_kb);
                b[p * 2][0] = r[0]; b[p * 2][1] = r[1];
                b[p * 2 + 1][0] = r[2]; b[p * 2 + 1][1] = r[3];
            }
            #pragma unroll
            for (int i = 0; i < 4; i++)
                #pragma unroll
                for (int j = 0; j < 4; j++)
                    mma16816(acc[i][j], a[i], b[j]);
        }
    }

    // epilogue: tanh(acc + bias) -> C
    #pragma unroll
    for (int j = 0; j < 4; j++) {
        const int col = nBase + warp_n * 32 + j * 8 + (lane & 3) * 2;
        const float bv0 = bias[col], bv1 = bias[col + 1];
        #pragma unroll
        for (int i = 0; i < 4; i++) {
            const int r0 = mBase + warp_m * 64 + i * 16 + (lane >> 2);
            float2 o0, o1;
            o0.x = tanh_acc(acc[i][j][0] + bv0);
            o0.y = tanh_acc(acc[i][j][1] + bv1);
            o1.x = tanh_acc(acc[i][j][2] + bv0);
            o1.y = tanh_acc(acc[i][j][3] + bv1);
            *(float2*)&C[(size_t)r0 * Ng + col]       = o0;
            *(float2*)&C[(size_t)(r0 + 8) * Ng + col] = o1;
        }
    }
#undef LOAD_STAGE
}

// ---------------------------------------------------------------------------
// prep: A' = [hi | hi | lo] per row from fp32 src (+shift)
// ---------------------------------------------------------------------------
__global__ void split_rows_kernel(const float* __restrict__ src,
                                  __nv_bfloat16* __restrict__ dst,
                                  int srcStride, float shift)
{
    const int idx = blockIdx.x * 256 + threadIdx.x;   // BB*512
    const int b = idx >> 9, s = idx & 511;
    const float v = src[(size_t)b * srcStride + s] + shift;
    const __nv_bfloat16 hi = __float2bfloat16(v);
    const float lo = v - __bfloat162float(hi);
    __nv_bfloat16* d = dst + (size_t)b * KP;
    d[s] = hi; d[512 + s] = hi; d[1024 + s] = __float2bfloat16(lo);
}

// prep: B'[n] = [hi | lo | hi] of W[:, n] (transpose + split)
__global__ void wsplit_kernel(const float* __restrict__ W,
                              __nv_bfloat16* __restrict__ Bp, int Ncols)
{
    __shared__ float t[32][33];
    const int n0 = blockIdx.x * 32, k0 = blockIdx.y * 32;
    const int tx = threadIdx.x & 31, ty = threadIdx.x >> 5;   // 32 x 8
    #pragma unroll
    for (int j = 0; j < 4; j++)
        t[ty + 8 * j][tx] = W[(size_t)(k0 + ty + 8 * j) * Ncols + n0 + tx];
    __syncthreads();
    #pragma unroll
    for (int j = 0; j < 4; j++) {
        const int n = n0 + ty + 8 * j;
        const int k = k0 + tx;
        const float v = t[tx][ty + 8 * j];
        const __nv_bfloat16 hi = __float2bfloat16(v);
        const float lo = v - __bfloat162float(hi);
        __nv_bfloat16* d = Bp + (size_t)n * KP;
        d[k] = hi; d[512 + k] = __float2bfloat16(lo); d[1024 + k] = hi;
    }
}

// ---------------------------------------------------------------------------
// spline epilogue (validated in round 1)
// ---------------------------------------------------------------------------
__global__ __launch_bounds__(512)
void spline_epilogue_kernel(const float* __restrict__ x_input,
                            const float* __restrict__ log_density,
                            const float* __restrict__ net,
                            float* __restrict__ out)
{
    const int b = blockIdx.x;
    const int s = threadIdx.x;

    const float* np = net + (size_t)b * NCC + s * 17;
    float v[17];
    #pragma unroll
    for (int j = 0; j < 17; j++) v[j] = np[j];

    float m = v[9];
    #pragma unroll
    for (int j = 10; j < 17; j++) m = fmaxf(m, v[j]);
    float w[8]; float wsum = 0.f;
    #pragma unroll
    for (int j = 0; j < 8; j++) { w[j] = __expf(v[9 + j] - m); wsum += w[j]; }
    const float winv = 1.f / wsum;
    #pragma unroll
    for (int j = 0; j < 8; j++) w[j] *= winv;

    float eh[9];
    #pragma unroll
    for (int j = 0; j < 9; j++) eh[j] = __expf(v[j]);
    float denom = 0.f;
    #pragma unroll
    for (int i = 0; i < 8; i++) denom += 0.5f * w[i] * (eh[i] + eh[i + 1]);
    const float dinv = 1.f / denom;
    float h[9];
    #pragma unroll
    for (int i = 0; i < 9; i++) h[i] = eh[i] * dinv;

    const float xa = x_input[(size_t)b * 1024 + s];
    const float xb = x_input[(size_t)b * 1024 + 512 + s];

    int cnt = (-EPSK < xb) ? 1 : 0;
    float cs = 0.f;
    #pragma unroll
    for (int i = 0; i < 8; i++) { cs += w[i]; cnt += (cs < xb) ? 1 : 0; }
    int k = cnt - 1;
    k = k < 0 ? 0 : (k > 7 ? 7 : k);

    float xk = 0.f, pk = 0.f, wk = 0.f, hk = 0.f, hk1 = 0.f;
    #pragma unroll
    for (int i = 0; i < 8; i++) {
        const float area = 0.5f * w[i] * (h[i] + h[i + 1]);
        if (i < k)  { xk += w[i]; pk += area; }
        if (i == k) { wk = w[i]; hk = h[i]; hk1 = h[i + 1]; }
    }
    if (k == 0) xk = -EPSK;

    const float alpha = (xb - xk) / wk;
    const float phib  = pk + alpha * hk * wk + 0.5f * alpha * alpha * (hk1 - hk) * wk;
    const float lt    = __logf(fmaf(alpha, (hk1 - hk), hk));

    out[(size_t)b * 1024 + s]       = xa;
    out[(size_t)b * 1024 + 512 + s] = phib;

    __shared__ float red[16];
    float sum = lt;
    #pragma unroll
    for (int o = 16; o > 0; o >>= 1) sum += __shfl_xor_sync(0xffffffffu, sum, o);
    const int lane = s & 31, wid = s >> 5;
    if (lane == 0) red[wid] = sum;
    __syncthreads();
    if (s < 16) {
        float t = red[s];
        #pragma unroll
        for (int o = 8; o > 0; o >>= 1) t += __shfl_xor_sync(0xffffu, t, o);
        if (s == 0) out[(size_t)BB * 1024 + b] = log_density[b] - t;
    }
}

// ---------------------------------------------------------------------------
extern "C" void kernel_launch(void* const* d_in, const int* in_sizes, int n_in,
                              void* d_out, int out_size)
{
    const float* x  = (const float*)d_in[0];
    const float* ld = (const float*)d_in[1];
    const float* W1 = (const float*)d_in[2];
    const float* b1 = (const float*)d_in[3];
    const float* W2 = (const float*)d_in[4];
    const float* b2 = (const float*)d_in[5];
    float* out = (float*)d_out;

    float *hid, *net;
    __nv_bfloat16 *A1, *A2, *B1, *B2;
    cudaGetSymbolAddress((void**)&hid, g_hid);
    cudaGetSymbolAddress((void**)&net, g_net);
    cudaGetSymbolAddress((void**)&A1, g_A1);
    cudaGetSymbolAddress((void**)&A2, g_A2);
    cudaGetSymbolAddress((void**)&B1, g_B1);
    cudaGetSymbolAddress((void**)&B2, g_B2);

    cudaFuncSetAttribute(gemm_tc, cudaFuncAttributeMaxDynamicSharedMemorySize, DSMEM);

    split_rows_kernel<<<BB * 512 / 256, 256>>>(x, A1, 1024, -0.5f);
    wsplit_kernel<<<dim3(HH / 32, 512 / 32), 256>>>(W1, B1, HH);
    wsplit_kernel<<<dim3(NCC / 32, 512 / 32), 256>>>(W2, B2, NCC);

    // hid = tanh((x_a-0.5) @ W1 + b1)
    gemm_tc<<<dim3(HH / 128, BB / 128), 256, DSMEM>>>(A1, B1, b1, hid, HH);
    split_rows_kernel<<<BB * 512 / 256, 256>>>(hid, A2, 512, 0.0f);
    // net = tanh(hid @ W2 + b2)
    gemm_tc<<<dim3(NCC / 128, BB / 128), 256, DSMEM>>>(A2, B2, b2, net, NCC);

    spline_epilogue_kernel<<<BB, 512>>>(x, ld, net, out);
}

// round 5
// speedup vs baseline: 1.9667x; 1.1216x over previous
#include <cuda_runtime.h>
#include <cuda_bf16.h>
#include <stdint.h>
#include <math.h>

#define BB   8192
#define HH   512
#define NCC  8704          // S*(2K+1)
#define KP2  1024          // stored K: [hi 512 | lo 512]
#define EPSK 1e-6f

#define ROWB  80           // 64B data + 16B pad per smem row
#define REGN  (128 * ROWB) // 10240 per region (Ahi/Alo/Bhi/Blo)
#define STG   (4 * REGN)   // 40960 per stage
#define DSMEM (2 * STG)    // 81920

__device__ __align__(128) float         g_net[(size_t)BB * NCC];
__device__ __align__(128) __nv_bfloat16 g_A1[(size_t)BB * KP2];
__device__ __align__(128) __nv_bfloat16 g_A2[(size_t)BB * KP2];
__device__ __align__(128) __nv_bfloat16 g_B1[(size_t)HH * KP2];
__device__ __align__(128) __nv_bfloat16 g_B2[(size_t)NCC * KP2];

// ------------------------------ helpers ------------------------------------
__device__ __forceinline__ uint32_t smem_u32(const void* p) {
    uint32_t a;
    asm("{ .reg .u64 t; cvta.to.shared.u64 t, %1; cvt.u32.u64 %0, t; }" : "=r"(a) : "l"(p));
    return a;
}
#define CP16(dst, src) \
    asm volatile("cp.async.cg.shared.global [%0], [%1], 16;" :: "r"(dst), "l"(src))
#define CP_COMMIT() asm volatile("cp.async.commit_group;" ::: "memory")
#define CP_WAIT1()  asm volatile("cp.async.wait_group 1;" ::: "memory")

__device__ __forceinline__ void ldm_x4(uint32_t* r, uint32_t addr) {
    asm volatile("ldmatrix.sync.aligned.m8n8.x4.shared.b16 {%0,%1,%2,%3}, [%4];"
                 : "=r"(r[0]), "=r"(r[1]), "=r"(r[2]), "=r"(r[3]) : "r"(addr));
}
__device__ __forceinline__ void mma16816(float* c, const uint32_t* a, const uint32_t* b) {
    asm volatile(
        "mma.sync.aligned.m16n8k16.row.col.f32.bf16.bf16.f32 "
        "{%0,%1,%2,%3}, {%4,%5,%6,%7}, {%8,%9}, {%0,%1,%2,%3};"
        : "+f"(c[0]), "+f"(c[1]), "+f"(c[2]), "+f"(c[3])
        : "r"(a[0]), "r"(a[1]), "r"(a[2]), "r"(a[3]), "r"(b[0]), "r"(b[1]));
}
__device__ __forceinline__ float tanh_acc(float x) {
    float y = fminf(fmaxf(2.0f * x, -60.0f), 60.0f);
    float t = __expf(y);
    return __fdividef(t - 1.0f, t + 1.0f);
}

// ---------------------------------------------------------------------------
// C[m][n] = tanh( sum_k A[m][k]*B[n][k] + bias[n] )   via bf16 3-pass split:
//   Ahi*Bhi + Ahi*Blo + Alo*Bhi  (missing AloBlo term ~2^-18)
// A,B stored [hi(512) | lo(512)] bf16 row-major, row stride KP2.
// CTA tile 128x128, 8 warps (2m x 4n), warp tile 64x32, BK=32 original-k,
// 2-stage cp.async pipeline. SPLIT_OUT: write bf16 [hi|lo] instead of fp32.
// ---------------------------------------------------------------------------
template <bool SPLIT_OUT>
__global__ __launch_bounds__(256, 2)
void gemm_tc(const __nv_bfloat16* __restrict__ A, const __nv_bfloat16* __restrict__ Bm,
             const float* __restrict__ bias, void* __restrict__ Cv, int Ng)
{
    extern __shared__ char dyn[];
    const uint32_t dynB = smem_u32(dyn);
    const int tid  = threadIdx.x;
    const int lane = tid & 31, w = tid >> 5;
    const int warp_m = w & 1, warp_n = w >> 1;        // 2 x 4
    const int mBase = blockIdx.y * 128, nBase = blockIdx.x * 128;

    const char* Ag = (const char*)(A  + (size_t)mBase * KP2);
    const char* Bg = (const char*)(Bm + (size_t)nBase * KP2);

    const int lrow = tid >> 2;          // 0..63 (+64 second pass)
    const int lch  = (tid & 3) * 16;

#define LOAD_STAGE(c) do {                                                        \
    const uint32_t _s = dynB + ((c) & 1) * STG;                                   \
    const size_t _kb = (size_t)(c) * 64;                                          \
    _Pragma("unroll")                                                             \
    for (int _h = 0; _h < 2; _h++) {                                              \
        const int _r = lrow + _h * 64;                                            \
        const size_t _ra = (size_t)_r * (KP2 * 2);                                \
        CP16(_s + 0*REGN + _r*ROWB + lch, Ag + _ra +        _kb + lch);           \
        CP16(_s + 1*REGN + _r*ROWB + lch, Ag + _ra + 1024 + _kb + lch);           \
        CP16(_s + 2*REGN + _r*ROWB + lch, Bg + _ra +        _kb + lch);           \
        CP16(_s + 3*REGN + _r*ROWB + lch, Bg + _ra + 1024 + _kb + lch);           \
    }                                                                             \
} while (0)

    LOAD_STAGE(0); CP_COMMIT();
    LOAD_STAGE(1); CP_COMMIT();

    float acc[4][4][4];
    #pragma unroll
    for (int i = 0; i < 4; i++)
        #pragma unroll
        for (int j = 0; j < 4; j++)
            #pragma unroll
            for (int e = 0; e < 4; e++) acc[i][j][e] = 0.f;

    const int grp = lane >> 3, lr = lane & 7;
    const int a_row = warp_m * 64 + (grp & 1) * 8 + lr;
    const int a_kb  = (grp >> 1) * 16;
    const int b_row = warp_n * 32 + (grp >> 1) * 8 + lr;
    const int b_kb  = (grp & 1) * 16;

    const int NIT = 512 / 32;   // 16
    for (int c = 0; c < NIT; c++) {
        CP_WAIT1();
        __syncthreads();
        const uint32_t st = dynB + (c & 1) * STG;

        #pragma unroll
        for (int kk = 0; kk < 2; kk++) {
            const uint32_t ak = kk * 32 + a_kb;
            const uint32_t bk = kk * 32 + b_kb;
            uint32_t ahi[4][4], bhi[4][2], bx[4][2], alo[4][4];

            #pragma unroll
            for (int i = 0; i < 4; i++)
                ldm_x4(ahi[i], st + 0*REGN + (uint32_t)(a_row + i*16)*ROWB + ak);
            #pragma unroll
            for (int p = 0; p < 2; p++) {
                uint32_t r[4];
                ldm_x4(r, st + 2*REGN + (uint32_t)(b_row + p*16)*ROWB + bk);
                bhi[p*2][0] = r[0]; bhi[p*2][1] = r[1];
                bhi[p*2+1][0] = r[2]; bhi[p*2+1][1] = r[3];
            }
            #pragma unroll
            for (int i = 0; i < 4; i++)
                #pragma unroll
                for (int j = 0; j < 4; j++)
                    mma16816(acc[i][j], ahi[i], bhi[j]);      // Ahi*Bhi

            #pragma unroll
            for (int p = 0; p < 2; p++) {
                uint32_t r[4];
                ldm_x4(r, st + 3*REGN + (uint32_t)(b_row + p*16)*ROWB + bk);
                bx[p*2][0] = r[0]; bx[p*2][1] = r[1];
                bx[p*2+1][0] = r[2]; bx[p*2+1][1] = r[3];
            }
            #pragma unroll
            for (int i = 0; i < 4; i++)
                #pragma unroll
                for (int j = 0; j < 4; j++)
                    mma16816(acc[i][j], ahi[i], bx[j]);       // Ahi*Blo

            #pragma unroll
            for (int i = 0; i < 4; i++)
                ldm_x4(alo[i], st + 1*REGN + (uint32_t)(a_row + i*16)*ROWB + ak);
            #pragma unroll
            for (int i = 0; i < 4; i++)
                #pragma unroll
                for (int j = 0; j < 4; j++)
                    mma16816(acc[i][j], alo[i], bhi[j]);      // Alo*Bhi
        }

        __syncthreads();
        if (c + 2 < NIT) LOAD_STAGE(c + 2);
        CP_COMMIT();                      // uniform group count per iter
    }
#undef LOAD_STAGE

    // ---------------- epilogue: tanh(acc + bias) ----------------
    #pragma unroll
    for (int j = 0; j < 4; j++) {
        const int col = nBase + warp_n * 32 + j * 8 + (lane & 3) * 2;
        const float bv0 = bias[col], bv1 = bias[col + 1];
        #pragma unroll
        for (int i = 0; i < 4; i++) {
            const int r0 = mBase + warp_m * 64 + i * 16 + (lane >> 2);
            float t00 = tanh_acc(acc[i][j][0] + bv0);
            float t01 = tanh_acc(acc[i][j][1] + bv1);
            float t10 = tanh_acc(acc[i][j][2] + bv0);
            float t11 = tanh_acc(acc[i][j][3] + bv1);
            if (SPLIT_OUT) {
                __nv_bfloat16* O = (__nv_bfloat16*)Cv;
                const int cl = col - nBase + nBase;   // absolute col
                __nv_bfloat162 h0, l0, h1, l1;
                h0.x = __float2bfloat16(t00); h0.y = __float2bfloat16(t01);
                l0.x = __float2bfloat16(t00 - __bfloat162float(h0.x));
                l0.y = __float2bfloat16(t01 - __bfloat162float(h0.y));
                h1.x = __float2bfloat16(t10); h1.y = __float2bfloat16(t11);
                l1.x = __float2bfloat16(t10 - __bfloat162float(h1.x));
                l1.y = __float2bfloat16(t11 - __bfloat162float(h1.y));
                *(__nv_bfloat162*)&O[(size_t)r0 * KP2 + cl]             = h0;
                *(__nv_bfloat162*)&O[(size_t)r0 * KP2 + 512 + cl]       = l0;
                *(__nv_bfloat162*)&O[(size_t)(r0 + 8) * KP2 + cl]       = h1;
                *(__nv_bfloat162*)&O[(size_t)(r0 + 8) * KP2 + 512 + cl] = l1;
            } else {
                float* Cf = (float*)Cv;
                float2 o0, o1;
                o0.x = t00; o0.y = t01; o1.x = t10; o1.y = t11;
                *(float2*)&Cf[(size_t)r0 * Ng + col]       = o0;
                *(float2*)&Cf[(size_t)(r0 + 8) * Ng + col] = o1;
            }
        }
    }
}

// ---------------------------------------------------------------------------
// prep: A1 = [hi | lo] of (x_a - 0.5)
// ---------------------------------------------------------------------------
__global__ void split_x_kernel(const float* __restrict__ src,
                               __nv_bfloat16* __restrict__ dst)
{
    const int idx = blockIdx.x * 256 + threadIdx.x;   // BB*512
    const int b = idx >> 9, s = idx & 511;
    const float v = src[(size_t)b * 1024 + s] - 0.5f;
    const __nv_bfloat16 hi = __float2bfloat16(v);
    __nv_bfloat16* d = dst + (size_t)b * KP2;
    d[s] = hi;
    d[512 + s] = __float2bfloat16(v - __bfloat162float(hi));
}

// prep: B'[n] = [hi | lo] of W[:, n] (transpose + split)
__global__ void wsplit_kernel(const float* __restrict__ W,
                              __nv_bfloat16* __restrict__ Bp, int Ncols)
{
    __shared__ float t[32][33];
    const int n0 = blockIdx.x * 32, k0 = blockIdx.y * 32;
    const int tx = threadIdx.x & 31, ty = threadIdx.x >> 5;   // 32 x 8
    #pragma unroll
    for (int j = 0; j < 4; j++)
        t[ty + 8 * j][tx] = W[(size_t)(k0 + ty + 8 * j) * Ncols + n0 + tx];
    __syncthreads();
    #pragma unroll
    for (int j = 0; j < 4; j++) {
        const int n = n0 + ty + 8 * j;
        const int k = k0 + tx;
        const float v = t[tx][ty + 8 * j];
        const __nv_bfloat16 hi = __float2bfloat16(v);
        __nv_bfloat16* d = Bp + (size_t)n * KP2;
        d[k] = hi;
        d[512 + k] = __float2bfloat16(v - __bfloat162float(hi));
    }
}

// ---------------------------------------------------------------------------
// spline epilogue (validated round 1)
// ---------------------------------------------------------------------------
__global__ __launch_bounds__(512)
void spline_epilogue_kernel(const float* __restrict__ x_input,
                            const float* __restrict__ log_density,
                            const float* __restrict__ net,
                            float* __restrict__ out)
{
    const int b = blockIdx.x;
    const int s = threadIdx.x;

    const float* np = net + (size_t)b * NCC + s * 17;
    float v[17];
    #pragma unroll
    for (int j = 0; j < 17; j++) v[j] = np[j];

    float m = v[9];
    #pragma unroll
    for (int j = 10; j < 17; j++) m = fmaxf(m, v[j]);
    float w[8]; float wsum = 0.f;
    #pragma unroll
    for (int j = 0; j < 8; j++) { w[j] = __expf(v[9 + j] - m); wsum += w[j]; }
    const float winv = 1.f / wsum;
    #pragma unroll
    for (int j = 0; j < 8; j++) w[j] *= winv;

    float eh[9];
    #pragma unroll
    for (int j = 0; j < 9; j++) eh[j] = __expf(v[j]);
    float denom = 0.f;
    #pragma unroll
    for (int i = 0; i < 8; i++) denom += 0.5f * w[i] * (eh[i] + eh[i + 1]);
    const float dinv = 1.f / denom;
    float h[9];
    #pragma unroll
    for (int i = 0; i < 9; i++) h[i] = eh[i] * dinv;

    const float xa = x_input[(size_t)b * 1024 + s];
    const float xb = x_input[(size_t)b * 1024 + 512 + s];

    int cnt = (-EPSK < xb) ? 1 : 0;
    float cs = 0.f;
    #pragma unroll
    for (int i = 0; i < 8; i++) { cs += w[i]; cnt += (cs < xb) ? 1 : 0; }
    int k = cnt - 1;
    k = k < 0 ? 0 : (k > 7 ? 7 : k);

    float xk = 0.f, pk = 0.f, wk = 0.f, hk = 0.f, hk1 = 0.f;
    #pragma unroll
    for (int i = 0; i < 8; i++) {
        const float area = 0.5f * w[i] * (h[i] + h[i + 1]);
        if (i < k)  { xk += w[i]; pk += area; }
        if (i == k) { wk = w[i]; hk = h[i]; hk1 = h[i + 1]; }
    }
    if (k == 0) xk = -EPSK;

    const float alpha = (xb - xk) / wk;
    const float phib  = pk + alpha * hk * wk + 0.5f * alpha * alpha * (hk1 - hk) * wk;
    const float lt    = __logf(fmaf(alpha, (hk1 - hk), hk));

    out[(size_t)b * 1024 + s]       = xa;
    out[(size_t)b * 1024 + 512 + s] = phib;

    __shared__ float red[16];
    float sum = lt;
    #pragma unroll
    for (int o = 16; o > 0; o >>= 1) sum += __shfl_xor_sync(0xffffffffu, sum, o);
    const int lane = s & 31, wid = s >> 5;
    if (lane == 0) red[wid] = sum;
    __syncthreads();
    if (s < 16) {
        float t = red[s];
        #pragma unroll
        for (int o = 8; o > 0; o >>= 1) t += __shfl_xor_sync(0xffffu, t, o);
        if (s == 0) out[(size_t)BB * 1024 + b] = log_density[b] - t;
    }
}

// ---------------------------------------------------------------------------
extern "C" void kernel_launch(void* const* d_in, const int* in_sizes, int n_in,
                              void* d_out, int out_size)
{
    const float* x  = (const float*)d_in[0];
    const float* ld = (const float*)d_in[1];
    const float* W1 = (const float*)d_in[2];
    const float* b1 = (const float*)d_in[3];
    const float* W2 = (const float*)d_in[4];
    const float* b2 = (const float*)d_in[5];
    float* out = (float*)d_out;

    float* net;
    __nv_bfloat16 *A1, *A2, *B1, *B2;
    cudaGetSymbolAddress((void**)&net, g_net);
    cudaGetSymbolAddress((void**)&A1, g_A1);
    cudaGetSymbolAddress((void**)&A2, g_A2);
    cudaGetSymbolAddress((void**)&B1, g_B1);
    cudaGetSymbolAddress((void**)&B2, g_B2);

    cudaFuncSetAttribute(gemm_tc<true>,  cudaFuncAttributeMaxDynamicSharedMemorySize, DSMEM);
    cudaFuncSetAttribute(gemm_tc<false>, cudaFuncAttributeMaxDynamicSharedMemorySize, DSMEM);

    split_x_kernel<<<BB * 512 / 256, 256>>>(x, A1);
    wsplit_kernel<<<dim3(HH / 32, 512 / 32), 256>>>(W1, B1, HH);
    wsplit_kernel<<<dim3(NCC / 32, 512 / 32), 256>>>(W2, B2, NCC);

    // A2 = split(tanh((x_a-0.5) @ W1 + b1))   (fused split epilogue)
    gemm_tc<true><<<dim3(HH / 128, BB / 128), 256, DSMEM>>>(A1, B1, b1, A2, HH);
    // net = tanh(hid @ W2 + b2)
    gemm_tc<false><<<dim3(NCC / 128, BB / 128), 256, DSMEM>>>(A2, B2, b2, net, NCC);

    spline_epilogue_kernel<<<BB, 512>>>(x, ld, net, out);
}